// round 2
// baseline (speedup 1.0000x reference)
#include <cuda_runtime.h>
#include <cuda_bf16.h>
#include <cstdint>

// ============================================================================
// GGRUCell on GB300 — mma.sync (HMMA) bf16 hi/lo-split GEMMs.
// (tcgen05 is unavailable: harness PTX targets compute_103 without the 'a'
//  feature set, so all tcgen05/TMEM instructions fail ptxas.)
//
// Math (update gate cancels exactly):
//   R   = sigmoid(prev @ Wr + inp[:,2H:]) * inp[:,:H]
//   out = mask * (tanh(R @ U + inp[:,:H]) + 1) + prev
// Each fp32 GEMM is computed as Ah@Bh + Ah@Bl + Al@Bh with bf16 planes.
// ============================================================================

#define HDIM   1024
#define BATCH  16384

static constexpr int M_TILE = 128;
static constexpr int N_TILE = 128;
static constexpr int KT     = 32;            // K-chunk
static constexpr int NC     = HDIM / KT;     // 32 chunks
static constexpr int SA     = 40;            // padded smem row stride (bf16 elems)

static constexpr int PLANE_BYTES = 128 * SA * 2;        // 10240
static constexpr int OFF_AH = 0;
static constexpr int OFF_AL = PLANE_BYTES;
static constexpr int OFF_BH = 2 * PLANE_BYTES;
static constexpr int OFF_BL = 3 * PLANE_BYTES;
static constexpr int STG_BYTES = 4 * PLANE_BYTES;       // 40960
static constexpr int SMEM_BYTES = 2 * STG_BYTES;        // 81920

// --------------------------------------------------------------------------
// PTX helpers (baseline sm_80+ instructions only)
// --------------------------------------------------------------------------
__device__ __forceinline__ uint32_t smem_to_u32(const void* p) {
    uint32_t a;
    asm("{ .reg .u64 t; cvta.to.shared.u64 t, %1; cvt.u32.u64 %0, t; }" : "=r"(a) : "l"(p));
    return a;
}
#define CP_ASYNC16(s, g) \
    asm volatile("cp.async.cg.shared.global [%0], [%1], 16;" :: "r"(s), "l"(g) : "memory")
#define CP_COMMIT() asm volatile("cp.async.commit_group;" ::: "memory")
#define CP_WAIT1()  asm volatile("cp.async.wait_group 1;" ::: "memory")
#define CP_WAIT0()  asm volatile("cp.async.wait_group 0;" ::: "memory")

#define LDSM_X4(r0, r1, r2, r3, addr) \
    asm volatile("ldmatrix.sync.aligned.m8n8.x4.shared.b16 {%0,%1,%2,%3}, [%4];" \
                 : "=r"(r0), "=r"(r1), "=r"(r2), "=r"(r3) : "r"(addr))

#define MMA_BF16(d, a, b) \
    asm volatile("mma.sync.aligned.m16n8k16.row.col.f32.bf16.bf16.f32 " \
                 "{%0,%1,%2,%3}, {%4,%5,%6,%7}, {%8,%9}, {%0,%1,%2,%3};" \
                 : "+f"((d)[0]), "+f"((d)[1]), "+f"((d)[2]), "+f"((d)[3]) \
                 : "r"((a)[0]), "r"((a)[1]), "r"((a)[2]), "r"((a)[3]), \
                   "r"((b)[0]), "r"((b)[1]))

// --------------------------------------------------------------------------
// Scratch (no cudaMalloc allowed)
// --------------------------------------------------------------------------
__device__ __nv_bfloat16 g_W1h[HDIM * HDIM];          // Wr^T hi  [n][k]
__device__ __nv_bfloat16 g_W1l[HDIM * HDIM];          // Wr^T lo
__device__ __nv_bfloat16 g_W2h[HDIM * HDIM];          // U^T hi
__device__ __nv_bfloat16 g_W2l[HDIM * HDIM];          // U^T lo
__device__ __nv_bfloat16 g_Ph[(size_t)BATCH * HDIM];  // prev hi
__device__ __nv_bfloat16 g_Pl[(size_t)BATCH * HDIM];  // prev lo
__device__ __nv_bfloat16 g_Rh[(size_t)BATCH * HDIM];  // R = reset*state, hi
__device__ __nv_bfloat16 g_Rl[(size_t)BATCH * HDIM];  // R lo

__device__ __forceinline__ uint32_t pack_bf16(__nv_bfloat16 a, __nv_bfloat16 b) {
    __nv_bfloat162 t; t.x = a; t.y = b;
    return *reinterpret_cast<uint32_t*>(&t);
}
__device__ __forceinline__ void split2(float x, float y, uint32_t& hp, uint32_t& lp) {
    __nv_bfloat16 hx = __float2bfloat16(x), hy = __float2bfloat16(y);
    __nv_bfloat16 lx = __float2bfloat16(x - __bfloat162float(hx));
    __nv_bfloat16 ly = __float2bfloat16(y - __bfloat162float(hy));
    hp = pack_bf16(hx, hy);
    lp = pack_bf16(lx, ly);
}

// --------------------------------------------------------------------------
// Weight transpose + hi/lo bf16 split: W[k][off+n] -> planes[n][k]
// --------------------------------------------------------------------------
__global__ void wtrans_kernel(const float* __restrict__ W, int ld, int off, int which) {
    __shared__ float tile[32][33];
    __nv_bfloat16* Oh = which ? g_W2h : g_W1h;
    __nv_bfloat16* Ol = which ? g_W2l : g_W1l;
    int tx = threadIdx.x, ty = threadIdx.y;
    int x0 = blockIdx.x * 32, y0 = blockIdx.y * 32;
#pragma unroll
    for (int j = 0; j < 32; j += 8)
        tile[ty + j][tx] = W[(y0 + ty + j) * ld + off + x0 + tx];
    __syncthreads();
#pragma unroll
    for (int j = 0; j < 32; j += 8) {
        float v = tile[tx][ty + j];                 // (k=y0+tx, n=x0+ty+j)
        int o = (x0 + ty + j) * HDIM + (y0 + tx);   // [n][k]
        __nv_bfloat16 h = __float2bfloat16(v);
        Oh[o] = h;
        Ol[o] = __float2bfloat16(v - __bfloat162float(h));
    }
}

// --------------------------------------------------------------------------
// prev (fp32) -> hi/lo bf16 planes, no transpose
// --------------------------------------------------------------------------
__global__ void psplit_kernel(const float* __restrict__ prev) {
    size_t i = ((size_t)blockIdx.x * 256 + threadIdx.x) * 4;
    float4 v = *reinterpret_cast<const float4*>(&prev[i]);
    uint32_t h01, l01, h23, l23;
    split2(v.x, v.y, h01, l01);
    split2(v.z, v.w, h23, l23);
    *reinterpret_cast<uint2*>(&g_Ph[i]) = make_uint2(h01, h23);
    *reinterpret_cast<uint2*>(&g_Pl[i]) = make_uint2(l01, l23);
}

// --------------------------------------------------------------------------
// GEMM: C[128x128] tile, 8 warps (2M x 4N), warp tile 64x32, K-chunk 32,
// cp.async 2-stage double buffer, ldmatrix + mma.sync bf16, 3-term split.
// --------------------------------------------------------------------------
template <bool FIRST>
__global__ void __launch_bounds__(256, 2)
gemm_kernel(const float* __restrict__ inp, const float* __restrict__ prev,
            const float* __restrict__ mask, float* __restrict__ out) {
    extern __shared__ char smem_raw[];
    const uint32_t sb = smem_to_u32(smem_raw);

    const int tid   = threadIdx.x;
    const int wid   = tid >> 5;
    const int lane  = tid & 31;
    const int warpM = wid & 1;        // 2 warps over M (64 rows each)
    const int warpN = wid >> 1;       // 4 warps over N (32 cols each)
    const int m0 = blockIdx.x * M_TILE;
    const int n0 = blockIdx.y * N_TILE;

    const __nv_bfloat16* AHg = FIRST ? g_Ph  : g_Rh;
    const __nv_bfloat16* ALg = FIRST ? g_Pl  : g_Rl;
    const __nv_bfloat16* BHg = FIRST ? g_W1h : g_W2h;
    const __nv_bfloat16* BLg = FIRST ? g_W1l : g_W2l;

    // per-thread cp.async mapping: 2 granules of 16B per plane per chunk
    const int rowq = tid >> 2;            // 0..63
    const int col8 = (tid & 3) * 8;       // k offset in elems

    auto issue_chunk = [&](int kc, int stage) {
        const uint32_t s0 = sb + stage * STG_BYTES;
#pragma unroll
        for (int r = 0; r < 2; r++) {
            const int row = rowq + r * 64;
            const size_t gA = (size_t)(m0 + row) * HDIM + kc * KT + col8;
            const size_t gB = (size_t)(n0 + row) * HDIM + kc * KT + col8;
            const uint32_t so = (uint32_t)(row * SA + col8) * 2;
            CP_ASYNC16(s0 + OFF_AH + so, AHg + gA);
            CP_ASYNC16(s0 + OFF_AL + so, ALg + gA);
            CP_ASYNC16(s0 + OFF_BH + so, BHg + gB);
            CP_ASYNC16(s0 + OFF_BL + so, BLg + gB);
        }
    };

    float acc[4][4][4];
#pragma unroll
    for (int i = 0; i < 4; i++)
#pragma unroll
        for (int j = 0; j < 4; j++)
#pragma unroll
            for (int k = 0; k < 4; k++) acc[i][j][k] = 0.f;

    issue_chunk(0, 0); CP_COMMIT();

    for (int c = 0; c < NC; c++) {
        if (c + 1 < NC) {
            issue_chunk(c + 1, (c + 1) & 1);
            CP_COMMIT();
            CP_WAIT1();
        } else {
            CP_WAIT0();
        }
        __syncthreads();

        const uint32_t s0  = sb + (c & 1) * STG_BYTES;
        const uint32_t sAh = s0 + OFF_AH, sAl = s0 + OFF_AL;
        const uint32_t sBh = s0 + OFF_BH, sBl = s0 + OFF_BL;

#pragma unroll
        for (int kb = 0; kb < KT; kb += 16) {
            // ---- B fragments: 4 n-subtiles x {b0,b1} per plane
            uint32_t bh[8], bl[8];
#pragma unroll
            for (int p = 0; p < 2; p++) {
                const int q    = lane >> 3;
                const int nrow = warpN * 32 + (p * 2 + (q >> 1)) * 8 + (lane & 7);
                const int kcol = kb + (q & 1) * 8;
                const uint32_t off = (uint32_t)(nrow * SA + kcol) * 2;
                LDSM_X4(bh[4 * p], bh[4 * p + 1], bh[4 * p + 2], bh[4 * p + 3], sBh + off);
                LDSM_X4(bl[4 * p], bl[4 * p + 1], bl[4 * p + 2], bl[4 * p + 3], sBl + off);
            }
            // ---- A fragments per m-subtile, then 3-term MMAs
#pragma unroll
            for (int mi = 0; mi < 4; mi++) {
                const int arow = warpM * 64 + mi * 16 + (lane & 15);
                const int kcol = kb + ((lane >> 4) << 3);
                const uint32_t off = (uint32_t)(arow * SA + kcol) * 2;
                uint32_t ah[4], al[4];
                LDSM_X4(ah[0], ah[1], ah[2], ah[3], sAh + off);
                LDSM_X4(al[0], al[1], al[2], al[3], sAl + off);
#pragma unroll
                for (int ni = 0; ni < 4; ni++) {
                    MMA_BF16(acc[mi][ni], ah, &bh[2 * ni]);
                    MMA_BF16(acc[mi][ni], ah, &bl[2 * ni]);
                    MMA_BF16(acc[mi][ni], al, &bh[2 * ni]);
                }
            }
        }
        __syncthreads();
    }

    // ---- epilogue ----
#pragma unroll
    for (int mi = 0; mi < 4; mi++) {
#pragma unroll
        for (int h = 0; h < 2; h++) {
            const int b = m0 + warpM * 64 + mi * 16 + h * 8 + (lane >> 2);
            float mval = 0.f;
            if (!FIRST) mval = __ldg(&mask[b]);
#pragma unroll
            for (int ni = 0; ni < 4; ni++) {
                const int n = n0 + warpN * 32 + ni * 8 + (lane & 3) * 2;
                const float v0 = acc[mi][ni][2 * h];
                const float v1 = acc[mi][ni][2 * h + 1];
                const float2 si = *reinterpret_cast<const float2*>(
                    &inp[(size_t)b * (3 * HDIM) + n]);
                if (FIRST) {
                    const float2 gi = *reinterpret_cast<const float2*>(
                        &inp[(size_t)b * (3 * HDIM) + 2 * HDIM + n]);
                    const float r0 = si.x / (1.f + __expf(-(v0 + gi.x)));
                    const float r1 = si.y / (1.f + __expf(-(v1 + gi.y)));
                    uint32_t hp, lp;
                    split2(r0, r1, hp, lp);
                    const size_t g = (size_t)b * HDIM + n;
                    *reinterpret_cast<uint32_t*>(&g_Rh[g]) = hp;
                    *reinterpret_cast<uint32_t*>(&g_Rl[g]) = lp;
                } else {
                    const float2 pv = *reinterpret_cast<const float2*>(
                        &prev[(size_t)b * HDIM + n]);
                    float2 o;
                    o.x = mval * (tanhf(v0 + si.x) + 1.f) + pv.x;
                    o.y = mval * (tanhf(v1 + si.y) + 1.f) + pv.y;
                    *reinterpret_cast<float2*>(&out[(size_t)b * HDIM + n]) = o;
                }
            }
        }
    }
}

// --------------------------------------------------------------------------
extern "C" void kernel_launch(void* const* d_in, const int* in_sizes, int n_in,
                              void* d_out, int out_size) {
    const float* inp  = (const float*)d_in[0];   // (B, 3H)
    const float* prev = (const float*)d_in[1];   // (B, H)
    const float* mask = (const float*)d_in[2];   // (B,)
    const float* Wur  = (const float*)d_in[3];   // (H, 2H)
    const float* U    = (const float*)d_in[4];   // (H, H)
    float* out = (float*)d_out;

    cudaFuncSetAttribute(gemm_kernel<true>,
                         cudaFuncAttributeMaxDynamicSharedMemorySize, SMEM_BYTES);
    cudaFuncSetAttribute(gemm_kernel<false>,
                         cudaFuncAttributeMaxDynamicSharedMemorySize, SMEM_BYTES);

    dim3 tb(32, 8), tg(HDIM / 32, HDIM / 32);
    wtrans_kernel<<<tg, tb>>>(Wur, 2 * HDIM, HDIM, 0);   // Wr = Wur[:, H:2H]
    wtrans_kernel<<<tg, tb>>>(U, HDIM, 0, 1);
    psplit_kernel<<<(BATCH * HDIM) / (256 * 4), 256>>>(prev);

    dim3 grid(BATCH / M_TILE, HDIM / N_TILE);
    gemm_kernel<true><<<grid, 256, SMEM_BYTES>>>(inp, prev, mask, out);
    gemm_kernel<false><<<grid, 256, SMEM_BYTES>>>(inp, prev, mask, out);
}